// round 10
// baseline (speedup 1.0000x reference)
#include <cuda_runtime.h>
#include <cuda_bf16.h>
#include <math.h>

#define SEQ 4096
#define DM  768
#define NH  12
#define HD  64

typedef unsigned int u32;

// tf32 round-to-nearest from fp32
__device__ __forceinline__ u32 f2tf(float f) {
    u32 u; asm("cvt.rna.tf32.f32 %0, %1;" : "=r"(u) : "f"(f)); return u;
}
__device__ __forceinline__ float f2tff(float f) { return __uint_as_float(f2tf(f)); }

// D(16x8) += A(16x8) * B(8x8), tf32 inputs, fp32 accum
#define MMA_TF32(d, a0, a1, a2, a3, b0, b1)                                        \
    asm volatile(                                                                  \
        "mma.sync.aligned.m16n8k8.row.col.f32.tf32.tf32.f32 "                      \
        "{%0,%1,%2,%3},{%4,%5,%6,%7},{%8,%9},{%0,%1,%2,%3};"                       \
        : "+f"((d)[0]), "+f"((d)[1]), "+f"((d)[2]), "+f"((d)[3])                   \
        : "r"(a0), "r"(a1), "r"(a2), "r"(a3), "r"(b0), "r"(b1))

// Scratch
__device__ float g_q[SEQ * DM];
__device__ float g_k[SEQ * DM];
__device__ float g_v[SEQ * DM];
__device__ float g_ctx[SEQ * DM];

// ---------------------------------------------------------------------------
// 128x128x32 GEMM via mma.sync tf32. 8 warps, warp = 32m x 64n. (round-7 ver)
// ---------------------------------------------------------------------------
#define AS_STR 36
#define BS_STR 136

__device__ __forceinline__ void gemm_mma(const float* __restrict__ A,
                                         const float* __restrict__ B,
                                         float* __restrict__ C,
                                         const float* __restrict__ bias) {
    __shared__ float As[128 * AS_STR];   // [m][k] 128x32
    __shared__ float Bs[32 * BS_STR];    // [k][n] 32x128

    const int tid = threadIdx.x;
    const int lane = tid & 31;
    const int wid = tid >> 5;
    const int gid = lane >> 2;
    const int tig = lane & 3;
    const int wm = wid >> 1;
    const int wn = wid & 1;
    const int m0 = blockIdx.y * 128;
    const int n0 = blockIdx.x * 128;

    float c[2][8][4];
#pragma unroll
    for (int i = 0; i < 2; i++)
#pragma unroll
        for (int f = 0; f < 8; f++)
#pragma unroll
            for (int j = 0; j < 4; j++) c[i][f][j] = 0.f;

    for (int k0 = 0; k0 < DM; k0 += 32) {
#pragma unroll
        for (int t = 0; t < 4; t++) {
            const int idx = tid + t * 256;
            const int m = idx >> 3;
            const int kq = (idx & 7) * 4;
            float4 a = *(const float4*)(A + (size_t)(m0 + m) * DM + k0 + kq);
            a.x = f2tff(a.x); a.y = f2tff(a.y); a.z = f2tff(a.z); a.w = f2tff(a.w);
            *(float4*)&As[m * AS_STR + kq] = a;

            const int kb = idx >> 5;
            const int nb = (idx & 31) * 4;
            float4 b = *(const float4*)(B + (size_t)(k0 + kb) * DM + n0 + nb);
            b.x = f2tff(b.x); b.y = f2tff(b.y); b.z = f2tff(b.z); b.w = f2tff(b.w);
            *(float4*)&Bs[kb * BS_STR + nb] = b;
        }
        __syncthreads();

#pragma unroll
        for (int k8 = 0; k8 < 4; k8++) {
            u32 a0[2], a1[2], a2[2], a3[2];
#pragma unroll
            for (int fm = 0; fm < 2; fm++) {
                const int rb = wm * 32 + fm * 16;
                const int kc = k8 * 8 + tig;
                a0[fm] = __float_as_uint(As[(rb + gid)     * AS_STR + kc]);
                a1[fm] = __float_as_uint(As[(rb + gid + 8) * AS_STR + kc]);
                a2[fm] = __float_as_uint(As[(rb + gid)     * AS_STR + kc + 4]);
                a3[fm] = __float_as_uint(As[(rb + gid + 8) * AS_STR + kc + 4]);
            }
#pragma unroll
            for (int f = 0; f < 8; f++) {
                const int nc = wn * 64 + f * 8 + gid;
                const u32 b0 = __float_as_uint(Bs[(k8 * 8 + tig)     * BS_STR + nc]);
                const u32 b1 = __float_as_uint(Bs[(k8 * 8 + tig + 4) * BS_STR + nc]);
                MMA_TF32(c[0][f], a0[0], a1[0], a2[0], a3[0], b0, b1);
                MMA_TF32(c[1][f], a0[1], a1[1], a2[1], a3[1], b0, b1);
            }
        }
        __syncthreads();
    }

#pragma unroll
    for (int fm = 0; fm < 2; fm++) {
        const int r1 = m0 + wm * 32 + fm * 16 + gid;
#pragma unroll
        for (int f = 0; f < 8; f++) {
            const int n = n0 + wn * 64 + f * 8 + 2 * tig;
            float b0 = 0.f, b1 = 0.f;
            if (bias) { b0 = bias[n]; b1 = bias[n + 1]; }
            *(float2*)(C + (size_t)r1 * DM + n) =
                make_float2(c[fm][f][0] + b0, c[fm][f][1] + b1);
            *(float2*)(C + (size_t)(r1 + 8) * DM + n) =
                make_float2(c[fm][f][2] + b0, c[fm][f][3] + b1);
        }
    }
}

__global__ __launch_bounds__(256, 2) void qkv_kernel(const float* __restrict__ x,
                                                     const float* __restrict__ wq,
                                                     const float* __restrict__ wk,
                                                     const float* __restrict__ wv) {
    const float* W;
    float* O;
    if (blockIdx.z == 0)      { W = wq; O = g_q; }
    else if (blockIdx.z == 1) { W = wk; O = g_k; }
    else                      { W = wv; O = g_v; }
    gemm_mma(x, W, O, nullptr);
}

__global__ __launch_bounds__(256, 2) void out_proj_kernel(const float* __restrict__ wo,
                                                          const float* __restrict__ bo,
                                                          float* __restrict__ out) {
    gemm_mma(g_ctx, wo, out, bo);
}

// ---------------------------------------------------------------------------
// Flash attention (causal), tf32 mma, register-resident P.
// CTA = 128 queries x 1 head; BK=64 key tiles; 8 warps; warp = 16 rows.
// S C-fragment is reused directly as the PV A-fragment; V rows stored with
// the sigma(j) = (j>>1) + ((j&1)<<2) permutation inside each 8-block.
// ---------------------------------------------------------------------------
#define BK 64
#define QS_STR 68
#define KS_STR 68
#define VS_STR 72
#define FLASH_SMEM ((128 * QS_STR + BK * KS_STR + BK * VS_STR) * 4)

__global__ __launch_bounds__(256, 2) void flash_kernel() {
    extern __shared__ float smf[];
    float* Qs = smf;                   // [q][d] 128x64, tf32*0.125
    float* Ks = Qs + 128 * QS_STR;     // [k][d] 64x64
    float* Vs = Ks + BK * KS_STR;      // [sigma(k)][d] 64x64

    const int tid = threadIdx.x;
    const int lane = tid & 31;
    const int wid = tid >> 5;
    const int gid = lane >> 2;
    const int tig = lane & 3;
    const int rw = wid * 16;
    const int qb = (gridDim.x - 1) - blockIdx.x;   // heavy CTAs first
    const int h = blockIdx.y;
    const int q0 = qb * 128;

    // Stage Q (scaled + tf32-rounded)
#pragma unroll
    for (int t = 0; t < 8; t++) {
        const int idx = tid + t * 256;
        const int r = idx >> 4;
        const int d4 = (idx & 15) * 4;
        float4 q = *(const float4*)(g_q + (size_t)(q0 + r) * DM + h * HD + d4);
        q.x = f2tff(q.x * 0.125f); q.y = f2tff(q.y * 0.125f);
        q.z = f2tff(q.z * 0.125f); q.w = f2tff(q.w * 0.125f);
        *(float4*)&Qs[r * QS_STR + d4] = q;
    }

    const int row1 = q0 + rw + gid;
    const int row2 = row1 + 8;
    float m1 = -1e30f, m2 = -1e30f, l1 = 0.f, l2 = 0.f;
    float o[8][4];
#pragma unroll
    for (int f = 0; f < 8; f++)
#pragma unroll
        for (int j = 0; j < 4; j++) o[f][j] = 0.f;

    const int ntile = 2 * qb + 2;
    for (int t = 0; t < ntile; t++) {
        const int k0g = t * BK;
        __syncthreads();   // smem reuse guard (covers Q staging on t=0)

        // Load K natural, V with key-row permutation (both tf32-rounded)
#pragma unroll
        for (int it = 0; it < 4; it++) {
            const int idx = tid + it * 256;
            const int r = idx >> 4;           // 0..63
            const int d4 = (idx & 15) * 4;
            float4 k = *(const float4*)(g_k + (size_t)(k0g + r) * DM + h * HD + d4);
            k.x = f2tff(k.x); k.y = f2tff(k.y); k.z = f2tff(k.z); k.w = f2tff(k.w);
            *(float4*)&Ks[r * KS_STR + d4] = k;
            float4 v = *(const float4*)(g_v + (size_t)(k0g + r) * DM + h * HD + d4);
            v.x = f2tff(v.x); v.y = f2tff(v.y); v.z = f2tff(v.z); v.w = f2tff(v.w);
            const int rp = (r & 56) + ((r & 7) >> 1) + ((r & 1) << 2);  // sigma
            *(float4*)&Vs[rp * VS_STR + d4] = v;
        }
        __syncthreads();

        // S = Q K^T (8 key-frags of 8)
        float s[8][4];
#pragma unroll
        for (int f = 0; f < 8; f++)
#pragma unroll
            for (int j = 0; j < 4; j++) s[f][j] = 0.f;

#pragma unroll
        for (int d8 = 0; d8 < 8; d8++) {
            const int dc = d8 * 8 + tig;
            const u32 a0 = __float_as_uint(Qs[(rw + gid)     * QS_STR + dc]);
            const u32 a1 = __float_as_uint(Qs[(rw + gid + 8) * QS_STR + dc]);
            const u32 a2 = __float_as_uint(Qs[(rw + gid)     * QS_STR + dc + 4]);
            const u32 a3 = __float_as_uint(Qs[(rw + gid + 8) * QS_STR + dc + 4]);
#pragma unroll
            for (int f = 0; f < 8; f++) {
                const u32 b0 = __float_as_uint(Ks[(f * 8 + gid) * KS_STR + dc]);
                const u32 b1 = __float_as_uint(Ks[(f * 8 + gid) * KS_STR + dc + 4]);
                MMA_TF32(s[f], a0, a1, a2, a3, b0, b1);
            }
        }

        // Causal mask (last two tiles of this q-block only)
        if (t >= 2 * qb) {
#pragma unroll
            for (int f = 0; f < 8; f++) {
                const int cb = k0g + f * 8 + 2 * tig;
                if (cb     > row1) s[f][0] = -1e30f;
                if (cb + 1 > row1) s[f][1] = -1e30f;
                if (cb     > row2) s[f][2] = -1e30f;
                if (cb + 1 > row2) s[f][3] = -1e30f;
            }
        }

        // Online softmax (quad reductions)
        float mx1 = -1e30f, mx2 = -1e30f;
#pragma unroll
        for (int f = 0; f < 8; f++) {
            mx1 = fmaxf(mx1, fmaxf(s[f][0], s[f][1]));
            mx2 = fmaxf(mx2, fmaxf(s[f][2], s[f][3]));
        }
#pragma unroll
        for (int off = 1; off <= 2; off <<= 1) {
            mx1 = fmaxf(mx1, __shfl_xor_sync(0xffffffffu, mx1, off));
            mx2 = fmaxf(mx2, __shfl_xor_sync(0xffffffffu, mx2, off));
        }
        const float mn1 = fmaxf(m1, mx1);
        const float mn2 = fmaxf(m2, mx2);
        float rs1 = 0.f, rs2 = 0.f;
#pragma unroll
        for (int f = 0; f < 8; f++) {
            s[f][0] = __expf(s[f][0] - mn1);
            s[f][1] = __expf(s[f][1] - mn1);
            s[f][2] = __expf(s[f][2] - mn2);
            s[f][3] = __expf(s[f][3] - mn2);
            rs1 += s[f][0] + s[f][1];
            rs2 += s[f][2] + s[f][3];
        }
#pragma unroll
        for (int off = 1; off <= 2; off <<= 1) {
            rs1 += __shfl_xor_sync(0xffffffffu, rs1, off);
            rs2 += __shfl_xor_sync(0xffffffffu, rs2, off);
        }
        const float al1 = __expf(m1 - mn1);
        const float al2 = __expf(m2 - mn2);
        m1 = mn1; m2 = mn2;
        l1 = l1 * al1 + rs1;
        l2 = l2 * al2 + rs2;
#pragma unroll
        for (int f = 0; f < 8; f++) {
            o[f][0] *= al1; o[f][1] *= al1;
            o[f][2] *= al2; o[f][3] *= al2;
        }

        // O += P V : P fragments are the S fragments (with sigma'd V rows).
        // A-frag: a0=c0, a1=c2, a2=c1, a3=c3 (tf32-rounded).
#pragma unroll
        for (int k8 = 0; k8 < 8; k8++) {
            const u32 a0 = f2tf(s[k8][0]);
            const u32 a1 = f2tf(s[k8][2]);
            const u32 a2 = f2tf(s[k8][1]);
            const u32 a3 = f2tf(s[k8][3]);
#pragma unroll
            for (int f = 0; f < 8; f++) {
                const u32 b0 = __float_as_uint(Vs[(k8 * 8 + tig)     * VS_STR + f * 8 + gid]);
                const u32 b1 = __float_as_uint(Vs[(k8 * 8 + tig + 4) * VS_STR + f * 8 + gid]);
                MMA_TF32(o[f], a0, a1, a2, a3, b0, b1);
            }
        }
    }

    // Epilogue
    const float inv1 = 1.0f / l1;
    const float inv2 = 1.0f / l2;
#pragma unroll
    for (int f = 0; f < 8; f++) {
        const int d = h * HD + f * 8 + 2 * tig;
        *(float2*)(g_ctx + (size_t)(q0 + rw + gid) * DM + d) =
            make_float2(o[f][0] * inv1, o[f][1] * inv1);
        *(float2*)(g_ctx + (size_t)(q0 + rw + gid + 8) * DM + d) =
            make_float2(o[f][2] * inv2, o[f][3] * inv2);
    }
}

// ---------------------------------------------------------------------------
extern "C" void kernel_launch(void* const* d_in, const int* in_sizes, int n_in,
                              void* d_out, int out_size) {
    const float* x  = (const float*)d_in[0];
    const float* wq = (const float*)d_in[1];
    const float* wk = (const float*)d_in[2];
    const float* wv = (const float*)d_in[3];
    const float* wo = (const float*)d_in[4];
    const float* bo = (const float*)d_in[5];
    float* out = (float*)d_out;

    cudaFuncSetAttribute(flash_kernel, cudaFuncAttributeMaxDynamicSharedMemorySize,
                         FLASH_SMEM);

    qkv_kernel<<<dim3(DM / 128, SEQ / 128, 3), 256>>>(x, wq, wk, wv);
    flash_kernel<<<dim3(SEQ / 128, NH), 256, FLASH_SMEM>>>();
    out_proj_kernel<<<dim3(DM / 128, SEQ / 128), 256>>>(wo, bo, out);
}

// round 11
// speedup vs baseline: 1.3369x; 1.3369x over previous
#include <cuda_runtime.h>
#include <cuda_bf16.h>
#include <math.h>

#define SEQ 4096
#define DM  768
#define NH  12
#define HD  64

typedef unsigned int u32;

// tf32 round-to-nearest from fp32
__device__ __forceinline__ u32 f2tf(float f) {
    u32 u; asm("cvt.rna.tf32.f32 %0, %1;" : "=r"(u) : "f"(f)); return u;
}
__device__ __forceinline__ float f2tff(float f) { return __uint_as_float(f2tf(f)); }

// D(16x8) += A(16x8) * B(8x8), tf32 inputs, fp32 accum
#define MMA_TF32(d, a0, a1, a2, a3, b0, b1)                                        \
    asm volatile(                                                                  \
        "mma.sync.aligned.m16n8k8.row.col.f32.tf32.tf32.f32 "                      \
        "{%0,%1,%2,%3},{%4,%5,%6,%7},{%8,%9},{%0,%1,%2,%3};"                       \
        : "+f"((d)[0]), "+f"((d)[1]), "+f"((d)[2]), "+f"((d)[3])                   \
        : "r"(a0), "r"(a1), "r"(a2), "r"(a3), "r"(b0), "r"(b1))

__device__ __forceinline__ void ldsm4(u32& r0, u32& r1, u32& r2, u32& r3, u32 addr) {
    asm volatile("ldmatrix.sync.aligned.m8n8.x4.shared.b16 {%0,%1,%2,%3}, [%4];"
                 : "=r"(r0), "=r"(r1), "=r"(r2), "=r"(r3) : "r"(addr));
}

__device__ __forceinline__ u32 smaddr(const void* p) {
    return (u32)__cvta_generic_to_shared(p);
}

// Scratch
__device__ float g_q[SEQ * DM];
__device__ float g_k[SEQ * DM];
__device__ float g_v[SEQ * DM];
__device__ float g_vt[SEQ * DM];   // per-head transposed V: [(h*64+d)][seq]
__device__ float g_ctx[SEQ * DM];

// ---------------------------------------------------------------------------
// 128x128x32 GEMM via mma.sync tf32. 8 warps, warp = 32m x 64n. (round-7 ver)
// ---------------------------------------------------------------------------
#define AS_STR 36
#define BS_STR 136

__device__ __forceinline__ void gemm_mma(const float* __restrict__ A,
                                         const float* __restrict__ B,
                                         float* __restrict__ C,
                                         const float* __restrict__ bias) {
    __shared__ float As[128 * AS_STR];   // [m][k] 128x32
    __shared__ float Bs[32 * BS_STR];    // [k][n] 32x128

    const int tid = threadIdx.x;
    const int lane = tid & 31;
    const int wid = tid >> 5;
    const int gid = lane >> 2;
    const int tig = lane & 3;
    const int wm = wid >> 1;
    const int wn = wid & 1;
    const int m0 = blockIdx.y * 128;
    const int n0 = blockIdx.x * 128;

    float c[2][8][4];
#pragma unroll
    for (int i = 0; i < 2; i++)
#pragma unroll
        for (int f = 0; f < 8; f++)
#pragma unroll
            for (int j = 0; j < 4; j++) c[i][f][j] = 0.f;

    for (int k0 = 0; k0 < DM; k0 += 32) {
#pragma unroll
        for (int t = 0; t < 4; t++) {
            const int idx = tid + t * 256;
            const int m = idx >> 3;
            const int kq = (idx & 7) * 4;
            float4 a = *(const float4*)(A + (size_t)(m0 + m) * DM + k0 + kq);
            a.x = f2tff(a.x); a.y = f2tff(a.y); a.z = f2tff(a.z); a.w = f2tff(a.w);
            *(float4*)&As[m * AS_STR + kq] = a;

            const int kb = idx >> 5;
            const int nb = (idx & 31) * 4;
            float4 b = *(const float4*)(B + (size_t)(k0 + kb) * DM + n0 + nb);
            b.x = f2tff(b.x); b.y = f2tff(b.y); b.z = f2tff(b.z); b.w = f2tff(b.w);
            *(float4*)&Bs[kb * BS_STR + nb] = b;
        }
        __syncthreads();

#pragma unroll
        for (int k8 = 0; k8 < 4; k8++) {
            u32 a0[2], a1[2], a2[2], a3[2];
#pragma unroll
            for (int fm = 0; fm < 2; fm++) {
                const int rb = wm * 32 + fm * 16;
                const int kc = k8 * 8 + tig;
                a0[fm] = __float_as_uint(As[(rb + gid)     * AS_STR + kc]);
                a1[fm] = __float_as_uint(As[(rb + gid + 8) * AS_STR + kc]);
                a2[fm] = __float_as_uint(As[(rb + gid)     * AS_STR + kc + 4]);
                a3[fm] = __float_as_uint(As[(rb + gid + 8) * AS_STR + kc + 4]);
            }
#pragma unroll
            for (int f = 0; f < 8; f++) {
                const int nc = wn * 64 + f * 8 + gid;
                const u32 b0 = __float_as_uint(Bs[(k8 * 8 + tig)     * BS_STR + nc]);
                const u32 b1 = __float_as_uint(Bs[(k8 * 8 + tig + 4) * BS_STR + nc]);
                MMA_TF32(c[0][f], a0[0], a1[0], a2[0], a3[0], b0, b1);
                MMA_TF32(c[1][f], a0[1], a1[1], a2[1], a3[1], b0, b1);
            }
        }
        __syncthreads();
    }

#pragma unroll
    for (int fm = 0; fm < 2; fm++) {
        const int r1 = m0 + wm * 32 + fm * 16 + gid;
#pragma unroll
        for (int f = 0; f < 8; f++) {
            const int n = n0 + wn * 64 + f * 8 + 2 * tig;
            float b0 = 0.f, b1 = 0.f;
            if (bias) { b0 = bias[n]; b1 = bias[n + 1]; }
            *(float2*)(C + (size_t)r1 * DM + n) =
                make_float2(c[fm][f][0] + b0, c[fm][f][1] + b1);
            *(float2*)(C + (size_t)(r1 + 8) * DM + n) =
                make_float2(c[fm][f][2] + b0, c[fm][f][3] + b1);
        }
    }
}

__global__ __launch_bounds__(256, 2) void qkv_kernel(const float* __restrict__ x,
                                                     const float* __restrict__ wq,
                                                     const float* __restrict__ wk,
                                                     const float* __restrict__ wv) {
    const float* W;
    float* O;
    if (blockIdx.z == 0)      { W = wq; O = g_q; }
    else if (blockIdx.z == 1) { W = wk; O = g_k; }
    else                      { W = wv; O = g_v; }
    gemm_mma(x, W, O, nullptr);
}

__global__ __launch_bounds__(256, 2) void out_proj_kernel(const float* __restrict__ wo,
                                                          const float* __restrict__ bo,
                                                          float* __restrict__ out) {
    gemm_mma(g_ctx, wo, out, bo);
}

// ---------------------------------------------------------------------------
// V transpose: g_v [s][c] -> g_vt [c][s]
// ---------------------------------------------------------------------------
__global__ __launch_bounds__(256) void vt_kernel() {
    __shared__ float t[32][33];
    const int tx = threadIdx.x & 31;
    const int ty = threadIdx.x >> 5;
    const int s0 = blockIdx.x * 32;
    const int c0 = blockIdx.y * 32;
#pragma unroll
    for (int j = 0; j < 4; j++)
        t[ty + j * 8][tx] = g_v[(size_t)(s0 + ty + j * 8) * DM + c0 + tx];
    __syncthreads();
#pragma unroll
    for (int j = 0; j < 4; j++)
        g_vt[(size_t)(c0 + ty + j * 8) * SEQ + s0 + tx] = t[tx][ty + j * 8];
}

// ---------------------------------------------------------------------------
// Flash attention (causal) via mma.sync tf32 with LDSM fragment loads.
// CTA = 128 queries x 1 head, 128-key tiles, 8 warps; warp = 16 rows.
// Strides 68/132 floats: row-to-row shift = 4 banks -> LDSM conflict-free.
// ---------------------------------------------------------------------------
#define QS_STR 68
#define KS_STR 68
#define VT_STR 132
#define PS_STR 132
#define FLASH_SMEM ((128 * QS_STR + 128 * KS_STR + 64 * VT_STR + 128 * PS_STR) * 4)

__global__ __launch_bounds__(256, 1) void flash_kernel() {
    extern __shared__ float smf[];
    float* Qs = smf;                       // [q][d]   128x64
    float* Ks = Qs + 128 * QS_STR;         // [k][d]   128x64
    float* Vt = Ks + 128 * KS_STR;         // [d][k]   64x128
    float* Ps = Vt + 64 * VT_STR;          // [q][k]   128x128

    const int tid = threadIdx.x;
    const int lane = tid & 31;
    const int wid = tid >> 5;
    const int gid = lane >> 2;
    const int tig = lane & 3;
    const int rw = wid * 16;
    const int qb = (gridDim.x - 1) - blockIdx.x;   // heavy CTAs first
    const int h = blockIdx.y;
    const int q0 = qb * 128;

    // LDSM lane-address components
    const int arow = rw + (lane & 15);             // A-frag rows (m16)
    const int acol = (lane >> 4) * 4;              // cols +4 for upper half
    const int brow = (lane & 7) + ((lane & 16) >> 1);  // B-frag: pair-of-n8 rows
    const int bcol = (lane & 8) >> 1;                  // cols +4
    const u32 q_a = smaddr(&Qs[arow * QS_STR + acol]);
    const u32 p_a = smaddr(&Ps[arow * PS_STR + acol]);
    const u32 k_b = smaddr(&Ks[brow * KS_STR + bcol]);
    const u32 v_b = smaddr(&Vt[brow * VT_STR + bcol]);

    // Load Q (scaled by 1/sqrt(HD), tf32-rounded)
#pragma unroll
    for (int t = 0; t < 8; t++) {
        const int idx = tid + t * 256;
        const int r = idx >> 4;
        const int d4 = (idx & 15) * 4;
        float4 q = *(const float4*)(g_q + (size_t)(q0 + r) * DM + h * HD + d4);
        q.x = f2tff(q.x * 0.125f); q.y = f2tff(q.y * 0.125f);
        q.z = f2tff(q.z * 0.125f); q.w = f2tff(q.w * 0.125f);
        *(float4*)&Qs[r * QS_STR + d4] = q;
    }

    const int row1 = q0 + rw + gid;
    const int row2 = row1 + 8;
    float m1 = -1e30f, m2 = -1e30f, l1 = 0.f, l2 = 0.f;
    float o[8][4];
#pragma unroll
    for (int f = 0; f < 8; f++)
#pragma unroll
        for (int j = 0; j < 4; j++) o[f][j] = 0.f;

    for (int kb = 0; kb <= qb; kb++) {
        const int k0g = kb * 128;
        __syncthreads();   // prev PV done (iter0: Q stores done)

        // Load K (natural) and V^T (rows = d), tf32-rounded
#pragma unroll
        for (int t = 0; t < 8; t++) {
            const int idx = tid + t * 256;
            const int r = idx >> 4;
            const int d4 = (idx & 15) * 4;
            float4 k = *(const float4*)(g_k + (size_t)(k0g + r) * DM + h * HD + d4);
            k.x = f2tff(k.x); k.y = f2tff(k.y); k.z = f2tff(k.z); k.w = f2tff(k.w);
            *(float4*)&Ks[r * KS_STR + d4] = k;

            const int d = idx >> 5;              // 0..63
            const int s4 = (idx & 31) * 4;       // 0..124
            float4 v = *(const float4*)(g_vt + (size_t)(h * HD + d) * SEQ + k0g + s4);
            v.x = f2tff(v.x); v.y = f2tff(v.y); v.z = f2tff(v.z); v.w = f2tff(v.w);
            *(float4*)&Vt[d * VT_STR + s4] = v;
        }
        __syncthreads();

        // S = Q K^T : A-frag 1 LDSM/d8, B-frags 1 LDSM per f-pair
        float s[16][4];
#pragma unroll
        for (int f = 0; f < 16; f++)
#pragma unroll
            for (int j = 0; j < 4; j++) s[f][j] = 0.f;

#pragma unroll
        for (int d8 = 0; d8 < 8; d8++) {
            u32 a0, a1, a2, a3;
            ldsm4(a0, a1, a2, a3, q_a + d8 * 32);
#pragma unroll
            for (int fp = 0; fp < 8; fp++) {
                u32 b0, b1, b2, b3;
                ldsm4(b0, b1, b2, b3, k_b + fp * (16 * KS_STR * 4) + d8 * 32);
                MMA_TF32(s[2 * fp],     a0, a1, a2, a3, b0, b1);
                MMA_TF32(s[2 * fp + 1], a0, a1, a2, a3, b2, b3);
            }
        }

        // Causal mask (diag tile only)
        if (kb == qb) {
#pragma unroll
            for (int f = 0; f < 16; f++) {
                const int cb = k0g + f * 8 + 2 * tig;
                if (cb     > row1) s[f][0] = -1e30f;
                if (cb + 1 > row1) s[f][1] = -1e30f;
                if (cb     > row2) s[f][2] = -1e30f;
                if (cb + 1 > row2) s[f][3] = -1e30f;
            }
        }

        // Online softmax (quad reductions)
        float mx1 = -1e30f, mx2 = -1e30f;
#pragma unroll
        for (int f = 0; f < 16; f++) {
            mx1 = fmaxf(mx1, fmaxf(s[f][0], s[f][1]));
            mx2 = fmaxf(mx2, fmaxf(s[f][2], s[f][3]));
        }
#pragma unroll
        for (int off = 1; off <= 2; off <<= 1) {
            mx1 = fmaxf(mx1, __shfl_xor_sync(0xffffffffu, mx1, off));
            mx2 = fmaxf(mx2, __shfl_xor_sync(0xffffffffu, mx2, off));
        }
        const float mn1 = fmaxf(m1, mx1);
        const float mn2 = fmaxf(m2, mx2);
        float rs1 = 0.f, rs2 = 0.f;
#pragma unroll
        for (int f = 0; f < 16; f++) {
            s[f][0] = __expf(s[f][0] - mn1);
            s[f][1] = __expf(s[f][1] - mn1);
            s[f][2] = __expf(s[f][2] - mn2);
            s[f][3] = __expf(s[f][3] - mn2);
            rs1 += s[f][0] + s[f][1];
            rs2 += s[f][2] + s[f][3];
        }
#pragma unroll
        for (int off = 1; off <= 2; off <<= 1) {
            rs1 += __shfl_xor_sync(0xffffffffu, rs1, off);
            rs2 += __shfl_xor_sync(0xffffffffu, rs2, off);
        }
        const float al1 = __expf(m1 - mn1);
        const float al2 = __expf(m2 - mn2);
        m1 = mn1; m2 = mn2;
        l1 = l1 * al1 + rs1;
        l2 = l2 * al2 + rs2;
#pragma unroll
        for (int f = 0; f < 8; f++) {
            o[f][0] *= al1; o[f][1] *= al1;
            o[f][2] *= al2; o[f][3] *= al2;
        }
        // Store P (tf32)
#pragma unroll
        for (int f = 0; f < 16; f++) {
            const int cc = f * 8 + 2 * tig;
            *(float2*)&Ps[(rw + gid) * PS_STR + cc] =
                make_float2(f2tff(s[f][0]), f2tff(s[f][1]));
            *(float2*)&Ps[(rw + gid + 8) * PS_STR + cc] =
                make_float2(f2tff(s[f][2]), f2tff(s[f][3]));
        }
        __syncthreads();   // P visible

        // O += P V : A-frag 1 LDSM/k8, B-frags 1 LDSM per d-pair
#pragma unroll
        for (int k8 = 0; k8 < 16; k8++) {
            u32 a0, a1, a2, a3;
            ldsm4(a0, a1, a2, a3, p_a + k8 * 32);
#pragma unroll
            for (int fp = 0; fp < 4; fp++) {
                u32 b0, b1, b2, b3;
                ldsm4(b0, b1, b2, b3, v_b + fp * (16 * VT_STR * 4) + k8 * 32);
                MMA_TF32(o[2 * fp],     a0, a1, a2, a3, b0, b1);
                MMA_TF32(o[2 * fp + 1], a0, a1, a2, a3, b2, b3);
            }
        }
    }

    // Epilogue
    const float inv1 = 1.0f / l1;
    const float inv2 = 1.0f / l2;
#pragma unroll
    for (int f = 0; f < 8; f++) {
        const int d = h * HD + f * 8 + 2 * tig;
        *(float2*)(g_ctx + (size_t)(q0 + rw + gid) * DM + d) =
            make_float2(o[f][0] * inv1, o[f][1] * inv1);
        *(float2*)(g_ctx + (size_t)(q0 + rw + gid + 8) * DM + d) =
            make_float2(o[f][2] * inv2, o[f][3] * inv2);
    }
}

// ---------------------------------------------------------------------------
extern "C" void kernel_launch(void* const* d_in, const int* in_sizes, int n_in,
                              void* d_out, int out_size) {
    const float* x  = (const float*)d_in[0];
    const float* wq = (const float*)d_in[1];
    const float* wk = (const float*)d_in[2];
    const float* wv = (const float*)d_in[3];
    const float* wo = (const float*)d_in[4];
    const float* bo = (const float*)d_in[5];
    float* out = (float*)d_out;

    cudaFuncSetAttribute(flash_kernel, cudaFuncAttributeMaxDynamicSharedMemorySize,
                         FLASH_SMEM);

    qkv_kernel<<<dim3(DM / 128, SEQ / 128, 3), 256>>>(x, wq, wk, wv);
    vt_kernel<<<dim3(SEQ / 32, DM / 32), 256>>>();
    flash_kernel<<<dim3(SEQ / 128, NH), 256, FLASH_SMEM>>>();
    out_proj_kernel<<<dim3(DM / 128, SEQ / 128), 256>>>(wo, bo, out);
}

// round 12
// speedup vs baseline: 1.3909x; 1.0403x over previous
#include <cuda_runtime.h>
#include <cuda_bf16.h>
#include <math.h>

#define SEQ 4096
#define DM  768
#define NH  12
#define HD  64

typedef unsigned int u32;

// tf32 round-to-nearest from fp32
__device__ __forceinline__ u32 f2tf(float f) {
    u32 u; asm("cvt.rna.tf32.f32 %0, %1;" : "=r"(u) : "f"(f)); return u;
}
__device__ __forceinline__ float f2tff(float f) { return __uint_as_float(f2tf(f)); }

__device__ __forceinline__ float ex2(float x) {
    float y; asm("ex2.approx.f32 %0, %1;" : "=f"(y) : "f"(x)); return y;
}

// D(16x8) += A(16x8) * B(8x8), tf32 inputs, fp32 accum
#define MMA_TF32(d, a0, a1, a2, a3, b0, b1)                                        \
    asm volatile(                                                                  \
        "mma.sync.aligned.m16n8k8.row.col.f32.tf32.tf32.f32 "                      \
        "{%0,%1,%2,%3},{%4,%5,%6,%7},{%8,%9},{%0,%1,%2,%3};"                       \
        : "+f"((d)[0]), "+f"((d)[1]), "+f"((d)[2]), "+f"((d)[3])                   \
        : "r"(a0), "r"(a1), "r"(a2), "r"(a3), "r"(b0), "r"(b1))

__device__ __forceinline__ void ldsm4(u32& r0, u32& r1, u32& r2, u32& r3, u32 addr) {
    asm volatile("ldmatrix.sync.aligned.m8n8.x4.shared.b16 {%0,%1,%2,%3}, [%4];"
                 : "=r"(r0), "=r"(r1), "=r"(r2), "=r"(r3) : "r"(addr));
}

__device__ __forceinline__ u32 smaddr(const void* p) {
    return (u32)__cvta_generic_to_shared(p);
}

// Scratch
__device__ float g_q[SEQ * DM];
__device__ float g_k[SEQ * DM];
__device__ float g_v[SEQ * DM];
__device__ float g_ctx[SEQ * DM];

// ---------------------------------------------------------------------------
// 128x128x32 GEMM via mma.sync tf32. 8 warps, warp = 32m x 64n. (round-7 ver)
// ---------------------------------------------------------------------------
#define AS_STR 36
#define BS_STR 136

__device__ __forceinline__ void gemm_mma(const float* __restrict__ A,
                                         const float* __restrict__ B,
                                         float* __restrict__ C,
                                         const float* __restrict__ bias) {
    __shared__ float As[128 * AS_STR];   // [m][k] 128x32
    __shared__ float Bs[32 * BS_STR];    // [k][n] 32x128

    const int tid = threadIdx.x;
    const int lane = tid & 31;
    const int wid = tid >> 5;
    const int gid = lane >> 2;
    const int tig = lane & 3;
    const int wm = wid >> 1;
    const int wn = wid & 1;
    const int m0 = blockIdx.y * 128;
    const int n0 = blockIdx.x * 128;

    float c[2][8][4];
#pragma unroll
    for (int i = 0; i < 2; i++)
#pragma unroll
        for (int f = 0; f < 8; f++)
#pragma unroll
            for (int j = 0; j < 4; j++) c[i][f][j] = 0.f;

    for (int k0 = 0; k0 < DM; k0 += 32) {
#pragma unroll
        for (int t = 0; t < 4; t++) {
            const int idx = tid + t * 256;
            const int m = idx >> 3;
            const int kq = (idx & 7) * 4;
            float4 a = *(const float4*)(A + (size_t)(m0 + m) * DM + k0 + kq);
            a.x = f2tff(a.x); a.y = f2tff(a.y); a.z = f2tff(a.z); a.w = f2tff(a.w);
            *(float4*)&As[m * AS_STR + kq] = a;

            const int kb = idx >> 5;
            const int nb = (idx & 31) * 4;
            float4 b = *(const float4*)(B + (size_t)(k0 + kb) * DM + n0 + nb);
            b.x = f2tff(b.x); b.y = f2tff(b.y); b.z = f2tff(b.z); b.w = f2tff(b.w);
            *(float4*)&Bs[kb * BS_STR + nb] = b;
        }
        __syncthreads();

#pragma unroll
        for (int k8 = 0; k8 < 4; k8++) {
            u32 a0[2], a1[2], a2[2], a3[2];
#pragma unroll
            for (int fm = 0; fm < 2; fm++) {
                const int rb = wm * 32 + fm * 16;
                const int kc = k8 * 8 + tig;
                a0[fm] = __float_as_uint(As[(rb + gid)     * AS_STR + kc]);
                a1[fm] = __float_as_uint(As[(rb + gid + 8) * AS_STR + kc]);
                a2[fm] = __float_as_uint(As[(rb + gid)     * AS_STR + kc + 4]);
                a3[fm] = __float_as_uint(As[(rb + gid + 8) * AS_STR + kc + 4]);
            }
#pragma unroll
            for (int f = 0; f < 8; f++) {
                const int nc = wn * 64 + f * 8 + gid;
                const u32 b0 = __float_as_uint(Bs[(k8 * 8 + tig)     * BS_STR + nc]);
                const u32 b1 = __float_as_uint(Bs[(k8 * 8 + tig + 4) * BS_STR + nc]);
                MMA_TF32(c[0][f], a0[0], a1[0], a2[0], a3[0], b0, b1);
                MMA_TF32(c[1][f], a0[1], a1[1], a2[1], a3[1], b0, b1);
            }
        }
        __syncthreads();
    }

#pragma unroll
    for (int fm = 0; fm < 2; fm++) {
        const int r1 = m0 + wm * 32 + fm * 16 + gid;
#pragma unroll
        for (int f = 0; f < 8; f++) {
            const int n = n0 + wn * 64 + f * 8 + 2 * tig;
            float b0 = 0.f, b1 = 0.f;
            if (bias) { b0 = bias[n]; b1 = bias[n + 1]; }
            *(float2*)(C + (size_t)r1 * DM + n) =
                make_float2(c[fm][f][0] + b0, c[fm][f][1] + b1);
            *(float2*)(C + (size_t)(r1 + 8) * DM + n) =
                make_float2(c[fm][f][2] + b0, c[fm][f][3] + b1);
        }
    }
}

__global__ __launch_bounds__(256, 2) void qkv_kernel(const float* __restrict__ x,
                                                     const float* __restrict__ wq,
                                                     const float* __restrict__ wk,
                                                     const float* __restrict__ wv) {
    const float* W;
    float* O;
    if (blockIdx.z == 0)      { W = wq; O = g_q; }
    else if (blockIdx.z == 1) { W = wk; O = g_k; }
    else                      { W = wv; O = g_v; }
    gemm_mma(x, W, O, nullptr);
}

__global__ __launch_bounds__(256, 2) void out_proj_kernel(const float* __restrict__ wo,
                                                          const float* __restrict__ bo,
                                                          float* __restrict__ out) {
    gemm_mma(g_ctx, wo, out, bo);
}

// ---------------------------------------------------------------------------
// Flash attention (causal), tf32 mma, register-resident P (no P smem tile).
// CTA = 128 queries x 1 head, 128-key tiles, 8 warps; warp = 16 rows.
// S C-frags reused as PV A-frags; V key-rows read sigma-permuted
// (k-slot tig -> row 2*tig, tig+4 -> 2*tig+1). 2 CTAs/SM.
// exp in base-2: scale 0.125*log2(e) folded into Q.
// ---------------------------------------------------------------------------
#define QS_STR 68
#define KS_STR 68
#define VS_STR 68
#define FLASH_SMEM ((128 * QS_STR + 128 * KS_STR + 128 * VS_STR) * 4)
#define QSCALE 0.18033688011112042f   // 0.125 * log2(e)

__global__ __launch_bounds__(256, 2) void flash_kernel() {
    extern __shared__ float smf[];
    float* Qs = smf;                       // [q][d]   128x64
    float* Ks = Qs + 128 * QS_STR;         // [k][d]   128x64
    float* Vs = Ks + 128 * KS_STR;         // [k][d]   128x64

    const int tid = threadIdx.x;
    const int lane = tid & 31;
    const int wid = tid >> 5;
    const int gid = lane >> 2;
    const int tig = lane & 3;
    const int rw = wid * 16;
    const int qb = (gridDim.x - 1) - blockIdx.x;   // heavy CTAs first
    const int h = blockIdx.y;
    const int q0 = qb * 128;

    // LDSM lane-address components (same mapping as round 11)
    const int arow = rw + (lane & 15);
    const int acol = (lane >> 4) * 4;
    const int brow = (lane & 7) + ((lane & 16) >> 1);
    const int bcol = (lane & 8) >> 1;
    const u32 q_a = smaddr(&Qs[arow * QS_STR + acol]);
    const u32 k_b = smaddr(&Ks[brow * KS_STR + bcol]);

    // Load Q (scaled by 0.125*log2e, tf32-rounded)
#pragma unroll
    for (int t = 0; t < 8; t++) {
        const int idx = tid + t * 256;
        const int r = idx >> 4;
        const int d4 = (idx & 15) * 4;
        float4 q = *(const float4*)(g_q + (size_t)(q0 + r) * DM + h * HD + d4);
        q.x = f2tff(q.x * QSCALE); q.y = f2tff(q.y * QSCALE);
        q.z = f2tff(q.z * QSCALE); q.w = f2tff(q.w * QSCALE);
        *(float4*)&Qs[r * QS_STR + d4] = q;
    }

    const int row1 = q0 + rw + gid;
    const int row2 = row1 + 8;
    float m1 = -1e30f, m2 = -1e30f, l1 = 0.f, l2 = 0.f;
    float o[8][4];
#pragma unroll
    for (int f = 0; f < 8; f++)
#pragma unroll
        for (int j = 0; j < 4; j++) o[f][j] = 0.f;

    for (int kb = 0; kb <= qb; kb++) {
        const int k0g = kb * 128;
        __syncthreads();   // prev PV done reading Ks/Vs (iter0: Q staged)

        // Load K, V (natural layout, tf32-rounded)
#pragma unroll
        for (int t = 0; t < 8; t++) {
            const int idx = tid + t * 256;
            const int r = idx >> 4;
            const int d4 = (idx & 15) * 4;
            float4 k = *(const float4*)(g_k + (size_t)(k0g + r) * DM + h * HD + d4);
            k.x = f2tff(k.x); k.y = f2tff(k.y); k.z = f2tff(k.z); k.w = f2tff(k.w);
            *(float4*)&Ks[r * KS_STR + d4] = k;
            float4 v = *(const float4*)(g_v + (size_t)(k0g + r) * DM + h * HD + d4);
            v.x = f2tff(v.x); v.y = f2tff(v.y); v.z = f2tff(v.z); v.w = f2tff(v.w);
            *(float4*)&Vs[r * VS_STR + d4] = v;
        }
        __syncthreads();

        // S = Q K^T  (LDSM fragments)
        float s[16][4];
#pragma unroll
        for (int f = 0; f < 16; f++)
#pragma unroll
            for (int j = 0; j < 4; j++) s[f][j] = 0.f;

#pragma unroll
        for (int d8 = 0; d8 < 8; d8++) {
            u32 a0, a1, a2, a3;
            ldsm4(a0, a1, a2, a3, q_a + d8 * 32);
#pragma unroll
            for (int fp = 0; fp < 8; fp++) {
                u32 b0, b1, b2, b3;
                ldsm4(b0, b1, b2, b3, k_b + fp * (16 * KS_STR * 4) + d8 * 32);
                MMA_TF32(s[2 * fp],     a0, a1, a2, a3, b0, b1);
                MMA_TF32(s[2 * fp + 1], a0, a1, a2, a3, b2, b3);
            }
        }

        // Causal mask (diag tile only)
        if (kb == qb) {
#pragma unroll
            for (int f = 0; f < 16; f++) {
                const int cb = k0g + f * 8 + 2 * tig;
                if (cb     > row1) s[f][0] = -1e30f;
                if (cb + 1 > row1) s[f][1] = -1e30f;
                if (cb     > row2) s[f][2] = -1e30f;
                if (cb + 1 > row2) s[f][3] = -1e30f;
            }
        }

        // Online softmax (base-2, quad reductions)
        float mx1 = -1e30f, mx2 = -1e30f;
#pragma unroll
        for (int f = 0; f < 16; f++) {
            mx1 = fmaxf(mx1, fmaxf(s[f][0], s[f][1]));
            mx2 = fmaxf(mx2, fmaxf(s[f][2], s[f][3]));
        }
#pragma unroll
        for (int off = 1; off <= 2; off <<= 1) {
            mx1 = fmaxf(mx1, __shfl_xor_sync(0xffffffffu, mx1, off));
            mx2 = fmaxf(mx2, __shfl_xor_sync(0xffffffffu, mx2, off));
        }
        const float mn1 = fmaxf(m1, mx1);
        const float mn2 = fmaxf(m2, mx2);
        float rs1 = 0.f, rs2 = 0.f;
#pragma unroll
        for (int f = 0; f < 16; f++) {
            s[f][0] = ex2(s[f][0] - mn1);
            s[f][1] = ex2(s[f][1] - mn1);
            s[f][2] = ex2(s[f][2] - mn2);
            s[f][3] = ex2(s[f][3] - mn2);
            rs1 += s[f][0] + s[f][1];
            rs2 += s[f][2] + s[f][3];
        }
#pragma unroll
        for (int off = 1; off <= 2; off <<= 1) {
            rs1 += __shfl_xor_sync(0xffffffffu, rs1, off);
            rs2 += __shfl_xor_sync(0xffffffffu, rs2, off);
        }
        const float al1 = ex2(m1 - mn1);
        const float al2 = ex2(m2 - mn2);
        m1 = mn1; m2 = mn2;
        l1 = l1 * al1 + rs1;
        l2 = l2 * al2 + rs2;
#pragma unroll
        for (int f = 0; f < 8; f++) {
            o[f][0] *= al1; o[f][1] *= al1;
            o[f][2] *= al2; o[f][3] *= al2;
        }

        // O += P V : P = S frags (a = {c0,c2,c1,c3}); V rows sigma-permuted.
#pragma unroll
        for (int k8 = 0; k8 < 16; k8++) {
            const u32 a0 = f2tf(s[k8][0]);
            const u32 a1 = f2tf(s[k8][2]);
            const u32 a2 = f2tf(s[k8][1]);
            const u32 a3 = f2tf(s[k8][3]);
            const float* vr0 = &Vs[(k8 * 8 + 2 * tig) * VS_STR];      // slot tig
            const float* vr1 = vr0 + VS_STR;                          // slot tig+4
#pragma unroll
            for (int f = 0; f < 8; f++) {
                const u32 b0 = __float_as_uint(vr0[f * 8 + gid]);
                const u32 b1 = __float_as_uint(vr1[f * 8 + gid]);
                MMA_TF32(o[f], a0, a1, a2, a3, b0, b1);
            }
        }
    }

    // Epilogue
    const float inv1 = 1.0f / l1;
    const float inv2 = 1.0f / l2;
#pragma unroll
    for (int f = 0; f < 8; f++) {
        const int d = h * HD + f * 8 + 2 * tig;
        *(float2*)(g_ctx + (size_t)(q0 + rw + gid) * DM + d) =
            make_float2(o[f][0] * inv1, o[f][1] * inv1);
        *(float2*)(g_ctx + (size_t)(q0 + rw + gid + 8) * DM + d) =
            make_float2(o[f][2] * inv2, o[f][3] * inv2);
    }
}

// ---------------------------------------------------------------------------
extern "C" void kernel_launch(void* const* d_in, const int* in_sizes, int n_in,
                              void* d_out, int out_size) {
    const float* x  = (const float*)d_in[0];
    const float* wq = (const float*)d_in[1];
    const float* wk = (const float*)d_in[2];
    const float* wv = (const float*)d_in[3];
    const float* wo = (const float*)d_in[4];
    const float* bo = (const float*)d_in[5];
    float* out = (float*)d_out;

    cudaFuncSetAttribute(flash_kernel, cudaFuncAttributeMaxDynamicSharedMemorySize,
                         FLASH_SMEM);

    qkv_kernel<<<dim3(DM / 128, SEQ / 128, 3), 256>>>(x, wq, wk, wv);
    flash_kernel<<<dim3(SEQ / 128, NH), 256, FLASH_SMEM>>>();
    out_proj_kernel<<<dim3(DM / 128, SEQ / 128), 256>>>(wo, bo, out);
}